// round 16
// baseline (speedup 1.0000x reference)
#include <cuda_runtime.h>
#include <math.h>

// Problem constants (fixed by the dataset)
#define Bn 2048
#define Dn 1024
#define Hn 2048
#define En 16
#define Wn 4
#define Rn 8
#define MAXK 4
#define CANDMAX 16
#define SCALE_C 1.0f

// ---------------- scratch (device globals; no allocation allowed) -----------
__device__ float g_hpre[Bn * Hn];
__device__ float g_outpre[Bn * Dn];
__device__ float g_cand_val[Bn * CANDMAX];
__device__ unsigned long long g_pack[Bn];
__device__ int   g_assigned_idx[Bn * MAXK];
__device__ float g_assigned_w[Bn * MAXK];
// bf16 (pair-packed) copies
__device__ unsigned g_z_bf[Bn * Dn / 2];
__device__ unsigned g_w1_bf[Hn * Dn / 2];
__device__ unsigned g_w2_bf[Dn * Hn / 2];
__device__ unsigned g_hpre_bf[Bn * Hn / 2];
__device__ unsigned g_a1_bf[En * Wn * Rn * Dn / 2];
__device__ unsigned g_b1_bf[En * Wn * Hn * Rn / 2];
__device__ unsigned g_a2_bf[En * Wn * Rn * Hn / 2];
__device__ unsigned g_b2_bf[En * Wn * Dn * Rn / 2];

// ---------------- output layout ----------------
struct Outs {
    float *z, *probs, *mask, *aidx, *aw, *chr, *ev_e, *ev_a;
};
__host__ __device__ __forceinline__ Outs make_outs(float* o, int k) {
    Outs s;
    s.z     = o; o += Bn * Dn;
    s.probs = o; o += Bn * En;
    s.mask  = o; o += Bn * En;
    s.aidx  = o; o += Bn * k;
    s.aw    = o; o += Bn * k;
    s.chr   = o; o += 1;
    s.ev_e  = o; o += (size_t)k * Bn;
    s.ev_a  = o;
    return s;
}

__device__ __forceinline__ float warp_reduce(float v) {
    #pragma unroll
    for (int off = 16; off; off >>= 1) v += __shfl_xor_sync(0xffffffffu, v, off);
    return v;
}
__device__ __forceinline__ float silu_f(float x) { return x / (1.0f + __expf(-x)); }

__device__ __forceinline__ unsigned pack_bf16(float lo, float hi) {
    unsigned r;
    asm("cvt.rn.bf16x2.f32 %0, %1, %2;" : "=r"(r) : "f"(hi), "f"(lo));
    return r;
}
__device__ __forceinline__ float bf_lo(unsigned u) { return __uint_as_float(u << 16); }
__device__ __forceinline__ float bf_hi(unsigned u) { return __uint_as_float(u & 0xffff0000u); }

__device__ __forceinline__ void mma_bf16(float* d, const unsigned* a, const unsigned* b) {
    asm volatile(
        "mma.sync.aligned.m16n8k16.row.col.f32.bf16.bf16.f32 "
        "{%0,%1,%2,%3}, {%4,%5,%6,%7}, {%8,%9}, {%0,%1,%2,%3};"
        : "+f"(d[0]), "+f"(d[1]), "+f"(d[2]), "+f"(d[3])
        : "r"(a[0]), "r"(a[1]), "r"(a[2]), "r"(a[3]), "r"(b[0]), "r"(b[1]));
}

__device__ __forceinline__ void cp_async16(unsigned* smem_dst, const void* gmem_src) {
    unsigned saddr = (unsigned)__cvta_generic_to_shared(smem_dst);
    asm volatile("cp.async.cg.shared.global [%0], [%1], 16;" :: "r"(saddr), "l"(gmem_src));
}
#define CP_COMMIT() asm volatile("cp.async.commit_group;")
#define CP_WAIT1()  asm volatile("cp.async.wait_group 1;")
#define GROUP_BAR(id) asm volatile("bar.sync %0, 128;" :: "r"(id) : "memory")

// =====================================================================
// Convert kernel: fp32 -> bf16x2-packed copies (one-time, elementwise).
// =====================================================================
#define CV0 (Bn * Dn / 2)
#define CV1 (CV0 + Hn * Dn / 2)
#define CV2 (CV1 + Dn * Hn / 2)
#define CV3 (CV2 + En * Wn * Rn * Dn / 2)
#define CV4 (CV3 + En * Wn * Hn * Rn / 2)
#define CV5 (CV4 + En * Wn * Rn * Hn / 2)
#define CV6 (CV5 + En * Wn * Dn * Rn / 2)

__global__ void __launch_bounds__(256)
convert_kernel(const float* __restrict__ z,  const float* __restrict__ w1,
               const float* __restrict__ w2, const float* __restrict__ a1,
               const float* __restrict__ b1, const float* __restrict__ a2,
               const float* __restrict__ b2) {
    for (int idx = blockIdx.x * 256 + threadIdx.x; idx < CV6; idx += gridDim.x * 256) {
        const float2* s; unsigned* d; int off;
        if      (idx < CV0) { s = (const float2*)z;  d = g_z_bf;  off = idx; }
        else if (idx < CV1) { s = (const float2*)w1; d = g_w1_bf; off = idx - CV0; }
        else if (idx < CV2) { s = (const float2*)w2; d = g_w2_bf; off = idx - CV1; }
        else if (idx < CV3) { s = (const float2*)a1; d = g_a1_bf; off = idx - CV2; }
        else if (idx < CV4) { s = (const float2*)b1; d = g_b1_bf; off = idx - CV3; }
        else if (idx < CV5) { s = (const float2*)a2; d = g_a2_bf; off = idx - CV4; }
        else                { s = (const float2*)b2; d = g_b2_bf; off = idx - CV5; }
        float2 v = s[off];
        d[off] = pack_bf16(v.x, v.y);
    }
}

// =====================================================================
// Side work A: logits/softmax/top-cand (fp32), one warp per token.
// =====================================================================
__device__ void logits_body(int b, int lane,
                            const float* __restrict__ z,
                            const float* __restrict__ proto,
                            const float* __restrict__ ebias,
                            const int* __restrict__ topk_p,
                            const int* __restrict__ ban_p,
                            const float* __restrict__ tau_p,
                            const float* __restrict__ eps_p,
                            float* __restrict__ d_out) {
    const float* zr = z + (size_t)b * Dn;

    float acc[En];
    #pragma unroll
    for (int e = 0; e < En; e++) acc[e] = 0.0f;
    for (int d = lane; d < Dn; d += 32) {
        float zv = zr[d];
        #pragma unroll
        for (int e = 0; e < En; e++) acc[e] += zv * proto[e * Dn + d];
    }
    #pragma unroll
    for (int e = 0; e < En; e++) acc[e] = warp_reduce(acc[e]);

    if (lane != 0) return;

    int k = *topk_p; if (k > En) k = En; if (k > MAXK) k = MAXK; if (k < 1) k = 1;
    int cand_k = 4 * k; if (cand_k < k) cand_k = k; if (cand_k > En) cand_k = En;
    int ban = *ban_p;
    float inv_tau = 1.0f / fmaxf(*tau_p, 1e-6f);
    float eps = *eps_p;

    float lg[En];
    float mx = -1e30f;
    #pragma unroll
    for (int e = 0; e < En; e++) {
        float v = acc[e] * inv_tau + ebias[e];
        if (e == ban) v = -1e9f;
        lg[e] = v;
        mx = fmaxf(mx, v);
    }
    float sum = 0.0f;
    #pragma unroll
    for (int e = 0; e < En; e++) { lg[e] = expf(lg[e] - mx); sum += lg[e]; }
    float inv = 1.0f / sum;

    Outs O = make_outs(d_out, k);
    float pr[En];
    #pragma unroll
    for (int e = 0; e < En; e++) {
        pr[e] = (1.0f - eps) * (lg[e] * inv) + eps / (float)En;
        O.probs[b * En + e] = pr[e];
        O.mask[b * En + e]  = 0.0f;
    }

    bool used[En];
    #pragma unroll
    for (int e = 0; e < En; e++) used[e] = false;
    unsigned long long pk = 0ull;
    for (int j = 0; j < cand_k; j++) {
        float bv = -1e30f; int bi = 0;
        for (int e = 0; e < En; e++)
            if (!used[e] && pr[e] > bv) { bv = pr[e]; bi = e; }
        used[bi] = true;
        g_cand_val[b * CANDMAX + j] = bv;
        pk |= ((unsigned long long)bi) << (4 * j);
    }
    g_pack[b] = pk;

    for (int s = 0; s < k; s++) {
        g_assigned_idx[b * MAXK + s] = -1;
        g_assigned_w[b * MAXK + s]   = 0.0f;
        O.aidx[b * k + s] = -1.0f;
        O.aw[b * k + s]   = 0.0f;
        O.ev_e[s * Bn + b] = -1.0f;
        O.ev_a[s * Bn + b] = -1.0f;
    }
}

// =====================================================================
// Side work B: batched greedy capacity router (single warp).
// =====================================================================
__device__ void route_body(int lane,
                           const int* __restrict__ topk_p,
                           const int* __restrict__ cap_p,
                           float* __restrict__ d_out) {
    int k = *topk_p; if (k > En) k = En; if (k > MAXK) k = MAXK; if (k < 1) k = 1;
    int cand_k = 4 * k; if (cand_k < k) cand_k = k; if (cand_k > En) cand_k = En;
    int cap_lim = *cap_p; if (cap_lim < 1) cap_lim = 1;

    Outs O = make_outs(d_out, k);

    int cap = 0;
    unsigned closed = 0;
    int hits = 0;

    int t0 = 0;
    while (t0 < Bn) {
        const int t = t0 + lane;
        const bool has = (t < Bn);
        unsigned long long pk = has ? g_pack[t] : 0ull;

        unsigned take = 0, slotcand = 0;
        int nslots = 0, myhits = 0;
        if (has) {
            for (int j = 0; j < cand_k; j++) {
                int e = (int)((pk >> (4 * j)) & 15ull);
                if (!((closed >> e) & 1u) && nslots < k) {
                    take |= (1u << e);
                    slotcand |= ((unsigned)j) << (4 * nslots);
                    if (j > 0) myhits++;
                    nslots++;
                }
            }
        }

        unsigned mybits = 0;
        #pragma unroll
        for (int e = 0; e < En; e++) {
            unsigned bb = __ballot_sync(0xffffffffu, (take >> e) & 1u);
            if (lane == e) mybits = bb;
        }
        int cnt = __popc(mybits);

        bool viol = (lane < En) && !((closed >> lane) & 1u) && (cap + cnt > cap_lim);
        unsigned vm = __ballot_sync(0xffffffffu, viol);
        int pstar = 32;
        if (vm) {
            int myp = 32;
            if (viol) {
                int rem = cap_lim - cap;
                unsigned m = mybits;
                for (int i = 0; i < rem; i++) m &= m - 1;
                myp = __ffs(m) - 1;
            }
            #pragma unroll
            for (int off = 16; off; off >>= 1) {
                int o = __shfl_xor_sync(0xffffffffu, myp, off);
                myp = min(myp, o);
            }
            pstar = myp;
        }

        unsigned commit_prefix = (pstar >= 32) ? 0xffffffffu : ((1u << pstar) - 1u);
        if (lane < En) cap += __popc(mybits & commit_prefix);

        if (has && lane < pstar) {
            for (int s = 0; s < nslots; s++) {
                int j = (int)((slotcand >> (4 * s)) & 15u);
                int e = (int)((pk >> (4 * j)) & 15ull);
                float v = g_cand_val[t * CANDMAX + j];
                g_assigned_idx[t * MAXK + s] = e;
                g_assigned_w[t * MAXK + s]   = v;
                O.aidx[t * k + s] = (float)e;
                O.aw[t * k + s]   = v;
                O.ev_e[s * Bn + t] = (float)e;
                O.mask[t * En + e] = 1.0f;
            }
            hits += myhits;
        }

        closed = __ballot_sync(0xffffffffu, (lane < En) && (cap >= cap_lim)) & 0xffffu;
        t0 += pstar;
    }

    #pragma unroll
    for (int off = 16; off; off >>= 1) hits += __shfl_xor_sync(0xffffffffu, hits, off);
    if (lane == 0) O.chr[0] = (float)hits / (float)(Bn * k);
}

// =====================================================================
// Fused BF16 GEMM (128x128x32, 3-stage cp.async, R14-exact mainloop).
// SIDE==1: logits side blocks (32 blocks = 256 warps; each warp loops
//          tokens at stride 256 -> 8 tokens/warp, hidden under GEMM).
// SIDE==2: router side block at bx==NX (by==0, warp 0).
// =====================================================================
#define TBM 128
#define TBN 128
#define TBK 32
#define PITCH 20
#define STG ((TBM + TBN) * PITCH)
#define NSTAGE 3

template <int ACT, int SIDE, int NX>
__global__ void __launch_bounds__(256, 2)
gemm_fused_kernel(const unsigned short* __restrict__ Abf,
                  const unsigned short* __restrict__ Wbf,
                  const float* __restrict__ bias, float* __restrict__ C,
                  unsigned* __restrict__ Cbf,
                  int M, int N, int K,
                  const float* __restrict__ z, const float* __restrict__ proto,
                  const float* __restrict__ ebias,
                  const int* __restrict__ topk_p, const int* __restrict__ ban_p,
                  const float* __restrict__ tau_p, const float* __restrict__ eps_p,
                  const int* __restrict__ cap_p,
                  float* __restrict__ d_out) {
    const int bx = blockIdx.x;
    const int by = blockIdx.y;
    const int tid = threadIdx.x;
    const int warp = tid >> 5;
    const int lane = tid & 31;

    if (bx >= NX) {
        if (SIDE == 1) {
            // 32 side blocks x 8 warps = 256 warps; token stride 256
            int wid = ((bx - NX) * gridDim.y + by) * 8 + warp;
            for (int b = wid; b < Bn; b += 256)
                logits_body(b, lane, z, proto, ebias, topk_p, ban_p, tau_p, eps_p, d_out);
        } else if (SIDE == 2) {
            if (by == 0 && warp == 0)
                route_body(lane, topk_p, cap_p, d_out);
        }
        return;
    }

    extern __shared__ unsigned smem_u[];

    const int g  = lane >> 2;
    const int tg = lane & 3;
    const int wq  = warp & 3;
    const int wn2 = warp >> 2;

    float acc[2][8][4];
    #pragma unroll
    for (int i = 0; i < 2; i++)
        #pragma unroll
        for (int j = 0; j < 8; j++)
            #pragma unroll
            for (int c = 0; c < 4; c++) acc[i][j][c] = 0.0f;

    auto issue = [&](int buf, int kt) {
        unsigned* base = smem_u + buf * STG;
        const int k0 = kt * TBK;
        #pragma unroll
        for (int i = 0; i < 4; i++) {
            int c = tid + i * 256;
            int row = c >> 2, ch = c & 3;
            const unsigned short* src;
            if (row < TBM) src = Abf + (size_t)(by * TBM + row) * K + k0 + ch * 8;
            else           src = Wbf + (size_t)(bx * TBN + row - TBM) * K + k0 + ch * 8;
            cp_async16(base + row * PITCH + ch * 4, (const void*)src);
        }
    };

    const int KIT = K / TBK;
    issue(0, 0); CP_COMMIT();
    if (1 < KIT) { issue(1, 1); } CP_COMMIT();

    int buf = 0;
    for (int kt = 0; kt < KIT; kt++) {
        CP_WAIT1();
        __syncthreads();
        if (kt + 2 < KIT) {
            int nb = buf + 2; if (nb >= NSTAGE) nb -= NSTAGE;
            issue(nb, kt + 2);
        }
        CP_COMMIT();

        const unsigned* AsC = smem_u + buf * STG;
        const unsigned* BsC = AsC + TBM * PITCH;

        #pragma unroll
        for (int kk = 0; kk < 2; kk++) {
            unsigned afr[2][4];
            #pragma unroll
            for (int mi = 0; mi < 2; mi++) {
                int row = wq * 32 + mi * 16 + g;
                afr[mi][0] = AsC[row * PITCH + kk * 8 + tg];
                afr[mi][1] = AsC[(row + 8) * PITCH + kk * 8 + tg];
                afr[mi][2] = AsC[row * PITCH + kk * 8 + tg + 4];
                afr[mi][3] = AsC[(row + 8) * PITCH + kk * 8 + tg + 4];
            }
            unsigned bfr[8][2];
            #pragma unroll
            for (int ni = 0; ni < 8; ni++) {
                int col = wn2 * 64 + ni * 8 + g;
                bfr[ni][0] = BsC[col * PITCH + kk * 8 + tg];
                bfr[ni][1] = BsC[col * PITCH + kk * 8 + tg + 4];
            }
            #pragma unroll
            for (int mi = 0; mi < 2; mi++)
                #pragma unroll
                for (int ni = 0; ni < 8; ni++)
                    mma_bf16(acc[mi][ni], afr[mi], bfr[ni]);
        }
        buf++; if (buf >= NSTAGE) buf = 0;
    }

    #pragma unroll
    for (int mi = 0; mi < 2; mi++) {
        int row0 = by * TBM + wq * 32 + mi * 16 + g;
        #pragma unroll
        for (int ni = 0; ni < 8; ni++) {
            int col = bx * TBN + wn2 * 64 + ni * 8 + 2 * tg;
            float b0 = bias[col], b1 = bias[col + 1];
            float v0 = acc[mi][ni][0] + b0;
            float v1 = acc[mi][ni][1] + b1;
            float v2 = acc[mi][ni][2] + b0;
            float v3 = acc[mi][ni][3] + b1;
            if (ACT) { v0 = silu_f(v0); v1 = silu_f(v1); v2 = silu_f(v2); v3 = silu_f(v3); }
            *(float2*)(&C[(size_t)row0 * N + col])       = make_float2(v0, v1);
            *(float2*)(&C[(size_t)(row0 + 8) * N + col]) = make_float2(v2, v3);
            if (ACT) {
                Cbf[((size_t)row0 * N + col) >> 1]       = pack_bf16(v0, v1);
                Cbf[((size_t)(row0 + 8) * N + col) >> 1] = pack_bf16(v2, v3);
            }
        }
    }
}

// =====================================================================
// Adapter kernel (exact round-13/14 version: 50.0 us measured).
// =====================================================================
__global__ void __launch_bounds__(256)
adapter_kernel(const float* __restrict__ z,
               const float* __restrict__ ak,
               const unsigned* __restrict__ a1b, const unsigned* __restrict__ b1b,
               const unsigned* __restrict__ a2b, const unsigned* __restrict__ b2b,
               const int* __restrict__ topk_p,
               float* __restrict__ d_out) {
    __shared__ float s_z[Dn];
    __shared__ float s_hp[Hn];
    __shared__ float s_t1[2][Rn];
    __shared__ float s_t2p[2][4][Rn];
    __shared__ float s_sc[2][Wn];
    __shared__ int   s_base[2];
    __shared__ float s_wgt[2];
    __shared__ int   s_valid[2];

    const int b = blockIdx.x;
    const int tid = threadIdx.x;
    const int lane = tid & 31;
    const int warp = tid >> 5;
    const int group = warp >> 2;
    const int wig = warp & 3;
    const int gt = tid & 127;
    const int gbar = 1 + group;

    int k = *topk_p; if (k > En) k = En; if (k > MAXK) k = MAXK; if (k < 1) k = 1;
    Outs O = make_outs(d_out, k);

    for (int i = tid; i < Dn / 4; i += 256)
        ((float4*)s_z)[i] = ((const float4*)(z + (size_t)b * Dn))[i];
    for (int i = tid; i < Hn / 4; i += 256)
        ((float4*)s_hp)[i] = ((const float4*)(g_hpre + (size_t)b * Hn))[i];

    float opre[Dn / 256];
    float accd[Dn / 256];
    #pragma unroll
    for (int i = 0; i < Dn / 256; i++) {
        opre[i] = g_outpre[(size_t)b * Dn + tid + i * 256];
        accd[i] = 0.0f;
    }
    __syncthreads();

    for (int s0 = 0; s0 < k; s0 += 2) {
        const int sA = s0 + group;
        const bool act = (sA < k);
        int e = -1;
        float wgt = 0.0f;
        if (act) {
            e   = g_assigned_idx[b * MAXK + sA];
            wgt = g_assigned_w[b * MAXK + sA];
        }
        const bool valid = act && (e >= 0);

        if (valid) {
            const float4* akr = (const float4*)(ak + (size_t)(e * Wn + wig) * Dn);
            float p = 0.0f;
            #pragma unroll
            for (int i = 0; i < Dn / 128; i++) {
                int idx = lane + i * 32;
                float4 a = akr[idx];
                float4 zz = ((const float4*)s_z)[idx];
                p += a.x * zz.x + a.y * zz.y + a.z * zz.z + a.w * zz.w;
            }
            p = warp_reduce(p);
            if (lane == 0) s_sc[group][wig] = p;
        }
        GROUP_BAR(gbar);

        if (gt == 0) {
            if (valid) {
                float bv = s_sc[group][0]; int bi = 0;
                #pragma unroll
                for (int w2 = 1; w2 < Wn; w2++)
                    if (s_sc[group][w2] > bv) { bv = s_sc[group][w2]; bi = w2; }
                s_base[group] = e * Wn + bi;
                s_wgt[group] = wgt;
                s_valid[group] = 1;
                O.ev_a[sA * Bn + b] = (float)bi;
            } else {
                s_valid[group] = 0;
            }
        }
        GROUP_BAR(gbar);

        const int base = s_base[group];

        if (valid) {
            const uint2* A1r0 = (const uint2*)a1b + ((size_t)base * Rn + 2 * wig) * (Dn / 4);
            const uint2* A1r1 = A1r0 + (Dn / 4);
            float q0 = 0.0f, q1 = 0.0f;
            #pragma unroll
            for (int i = 0; i < Dn / 128; i++) {
                int idx = lane + i * 32;
                float4 zz = ((const float4*)s_z)[idx];
                uint2 u0 = A1r0[idx], u1 = A1r1[idx];
                q0 += zz.x * bf_lo(u0.x) + zz.y * bf_hi(u0.x)
                    + zz.z * bf_lo(u0.y) + zz.w * bf_hi(u0.y);
                q1 += zz.x * bf_lo(u1.x) + zz.y * bf_hi(u1.x)
                    + zz.z * bf_lo(u1.y) + zz.w * bf_hi(u1.y);
            }
            q0 = warp_reduce(q0);
            q1 = warp_reduce(q1);
            if (lane == 0) { s_t1[group][2 * wig] = q0; s_t1[group][2 * wig + 1] = q1; }
        }
        GROUP_BAR(gbar);

        if (valid) {
            float t1r[Rn];
            #pragma unroll
            for (int r = 0; r < Rn; r++) t1r[r] = s_t1[group][r];
            float t2p[Rn];
            #pragma unroll
            for (int r = 0; r < Rn; r++) t2p[r] = 0.0f;
            const uint4* B1 = (const uint4*)b1b + (size_t)base * Hn;
            const unsigned* A2 = a2b + (size_t)base * Rn * (Hn / 2);
            #pragma unroll
            for (int i = 0; i < 8; i++) {
                int hp = wig * 256 + lane + i * 32;
                float2 h2 = *(const float2*)&s_hp[2 * hp];
                uint4 q0 = B1[2 * hp];
                uint4 q1 = B1[2 * hp + 1];
                float d10 = t1r[0] * bf_lo(q0.x) + t1r[1] * bf_hi(q0.x)
                          + t1r[2] * bf_lo(q0.y) + t1r[3] * bf_hi(q0.y)
                          + t1r[4] * bf_lo(q0.z) + t1r[5] * bf_hi(q0.z)
                          + t1r[6] * bf_lo(q0.w) + t1r[7] * bf_hi(q0.w);
                float d11 = t1r[0] * bf_lo(q1.x) + t1r[1] * bf_hi(q1.x)
                          + t1r[2] * bf_lo(q1.y) + t1r[3] * bf_hi(q1.y)
                          + t1r[4] * bf_lo(q1.z) + t1r[5] * bf_hi(q1.z)
                          + t1r[6] * bf_lo(q1.w) + t1r[7] * bf_hi(q1.w);
                float hv0 = silu_f(h2.x + d10 * SCALE_C);
                float hv1 = silu_f(h2.y + d11 * SCALE_C);
                #pragma unroll
                for (int r = 0; r < Rn; r++) {
                    unsigned u = A2[r * (Hn / 2) + hp];
                    t2p[r] += hv0 * bf_lo(u) + hv1 * bf_hi(u);
                }
            }
            #pragma unroll
            for (int r = 0; r < Rn; r++) t2p[r] = warp_reduce(t2p[r]);
            if (lane < Rn) s_t2p[group][wig][lane] = t2p[lane];
        }
        __syncthreads();

        #pragma unroll
        for (int gg = 0; gg < 2; gg++) {
            if (s_valid[gg]) {
                const int bs = s_base[gg];
                const float wg = s_wgt[gg];
                float t2r[Rn];
                #pragma unroll
                for (int r = 0; r < Rn; r++)
                    t2r[r] = s_t2p[gg][0][r] + s_t2p[gg][1][r]
                           + s_t2p[gg][2][r] + s_t2p[gg][3][r];
                const uint4* B2q = (const uint4*)b2b + (size_t)bs * Dn;
                #pragma unroll
                for (int i = 0; i < Dn / 256; i++) {
                    int d = tid + i * 256;
                    uint4 q = B2q[d];
                    float d2 = t2r[0] * bf_lo(q.x) + t2r[1] * bf_hi(q.x)
                             + t2r[2] * bf_lo(q.y) + t2r[3] * bf_hi(q.y)
                             + t2r[4] * bf_lo(q.z) + t2r[5] * bf_hi(q.z)
                             + t2r[6] * bf_lo(q.w) + t2r[7] * bf_hi(q.w);
                    accd[i] += wg * (opre[i] + d2 * SCALE_C);
                }
            }
        }
        __syncthreads();
    }

    #pragma unroll
    for (int i = 0; i < Dn / 256; i++) {
        int d = tid + i * 256;
        O.z[(size_t)b * Dn + d] = s_z[d] + accd[i];
    }
}

// =====================================================================
// launch
// =====================================================================
extern "C" void kernel_launch(void* const* d_in, const int* in_sizes, int n_in,
                              void* d_out, int out_size) {
    const float* z     = (const float*)d_in[0];
    const int*   topk  = (const int*)  d_in[1];
    const int*   cap   = (const int*)  d_in[2];
    const int*   ban   = (const int*)  d_in[3];
    const float* tau   = (const float*)d_in[4];
    const float* eps   = (const float*)d_in[5];
    const float* fc1w  = (const float*)d_in[6];
    const float* fc1b  = (const float*)d_in[7];
    const float* fc2w  = (const float*)d_in[8];
    const float* fc2b  = (const float*)d_in[9];
    const float* proto = (const float*)d_in[10];
    const float* ak    = (const float*)d_in[11];
    const float* ebias = (const float*)d_in[12];
    const float* a1    = (const float*)d_in[13];
    const float* b1    = (const float*)d_in[14];
    const float* a2    = (const float*)d_in[15];
    const float* b2    = (const float*)d_in[16];
    float* out = (float*)d_out;

    float *hpre_ptr, *outpre_ptr;
    unsigned *zb, *w1b, *w2b, *hpb, *a1b, *b1b, *a2b, *b2b;
    cudaGetSymbolAddress((void**)&hpre_ptr, g_hpre);
    cudaGetSymbolAddress((void**)&outpre_ptr, g_outpre);
    cudaGetSymbolAddress((void**)&zb,  g_z_bf);
    cudaGetSymbolAddress((void**)&w1b, g_w1_bf);
    cudaGetSymbolAddress((void**)&w2b, g_w2_bf);
    cudaGetSymbolAddress((void**)&hpb, g_hpre_bf);
    cudaGetSymbolAddress((void**)&a1b, g_a1_bf);
    cudaGetSymbolAddress((void**)&b1b, g_b1_bf);
    cudaGetSymbolAddress((void**)&a2b, g_a2_bf);
    cudaGetSymbolAddress((void**)&b2b, g_b2_bf);

    const int gemm_smem = NSTAGE * STG * sizeof(unsigned);  // 61440
    cudaFuncSetAttribute((const void*)gemm_fused_kernel<1, 1, 16>,
                         cudaFuncAttributeMaxDynamicSharedMemorySize, gemm_smem);
    cudaFuncSetAttribute((const void*)gemm_fused_kernel<0, 2, 8>,
                         cudaFuncAttributeMaxDynamicSharedMemorySize, gemm_smem);

    // 0) one-time fp32 -> bf16 conversion
    convert_kernel<<<2048, 256>>>(z, fc1w, fc2w, a1, b1, a2, b2);

    // 1) GEMM1 (h_pre + bf16 copy) + 32 logits side blocks.
    //    grid 18x16 = 288 blocks <= 296 slots -> single wave.
    gemm_fused_kernel<1, 1, 16><<<dim3(18, 16), 256, gemm_smem>>>(
        (const unsigned short*)zb, (const unsigned short*)w1b, fc1b,
        hpre_ptr, hpb, Bn, Hn, Dn,
        z, proto, ebias, topk, ban, tau, eps, cap, out);

    // 2) GEMM2 (out_pre) + router side block (144 + 16 = 160 blocks)
    gemm_fused_kernel<0, 2, 8><<<dim3(9, 16), 256, gemm_smem>>>(
        (const unsigned short*)hpb, (const unsigned short*)w2b, fc2b,
        outpre_ptr, nullptr, Bn, Dn, Hn,
        z, proto, ebias, topk, ban, tau, eps, cap, out);

    // 3) adapter select + LoRA deltas + final combine (R13/14 exact)
    adapter_kernel<<<Bn, 256>>>(z, ak, a1b, b1b, a2b, b2b, topk, out);
}

// round 17
// speedup vs baseline: 1.1926x; 1.1926x over previous
#include <cuda_runtime.h>
#include <math.h>

// Problem constants (fixed by the dataset)
#define Bn 2048
#define Dn 1024
#define Hn 2048
#define En 16
#define Wn 4
#define Rn 8
#define MAXK 4
#define CANDMAX 16
#define SCALE_C 1.0f

// ---------------- scratch (device globals; no allocation allowed) -----------
__device__ float g_hpre[Bn * Hn];
__device__ float g_outpre[Bn * Dn];
__device__ float g_cand_val[Bn * CANDMAX];
__device__ unsigned long long g_pack[Bn];
__device__ int   g_assigned_idx[Bn * MAXK];
__device__ float g_assigned_w[Bn * MAXK];
// bf16 (pair-packed) copies
__device__ unsigned g_z_bf[Bn * Dn / 2];
__device__ unsigned g_w1_bf[Hn * Dn / 2];
__device__ unsigned g_w2_bf[Dn * Hn / 2];
__device__ unsigned g_hpre_bf[Bn * Hn / 2];
__device__ unsigned g_a1_bf[En * Wn * Rn * Dn / 2];
__device__ unsigned g_b1_bf[En * Wn * Hn * Rn / 2];
__device__ unsigned g_a2_bf[En * Wn * Rn * Hn / 2];
__device__ unsigned g_b2_bf[En * Wn * Dn * Rn / 2];

// ---------------- output layout ----------------
struct Outs {
    float *z, *probs, *mask, *aidx, *aw, *chr, *ev_e, *ev_a;
};
__host__ __device__ __forceinline__ Outs make_outs(float* o, int k) {
    Outs s;
    s.z     = o; o += Bn * Dn;
    s.probs = o; o += Bn * En;
    s.mask  = o; o += Bn * En;
    s.aidx  = o; o += Bn * k;
    s.aw    = o; o += Bn * k;
    s.chr   = o; o += 1;
    s.ev_e  = o; o += (size_t)k * Bn;
    s.ev_a  = o;
    return s;
}

__device__ __forceinline__ float warp_reduce(float v) {
    #pragma unroll
    for (int off = 16; off; off >>= 1) v += __shfl_xor_sync(0xffffffffu, v, off);
    return v;
}
__device__ __forceinline__ float silu_f(float x) { return x / (1.0f + __expf(-x)); }

__device__ __forceinline__ unsigned pack_bf16(float lo, float hi) {
    unsigned r;
    asm("cvt.rn.bf16x2.f32 %0, %1, %2;" : "=r"(r) : "f"(hi), "f"(lo));
    return r;
}
__device__ __forceinline__ float bf_lo(unsigned u) { return __uint_as_float(u << 16); }
__device__ __forceinline__ float bf_hi(unsigned u) { return __uint_as_float(u & 0xffff0000u); }

__device__ __forceinline__ void mma_bf16(float* d, const unsigned* a, const unsigned* b) {
    asm volatile(
        "mma.sync.aligned.m16n8k16.row.col.f32.bf16.bf16.f32 "
        "{%0,%1,%2,%3}, {%4,%5,%6,%7}, {%8,%9}, {%0,%1,%2,%3};"
        : "+f"(d[0]), "+f"(d[1]), "+f"(d[2]), "+f"(d[3])
        : "r"(a[0]), "r"(a[1]), "r"(a[2]), "r"(a[3]), "r"(b[0]), "r"(b[1]));
}

__device__ __forceinline__ void cp_async16(unsigned* smem_dst, const void* gmem_src) {
    unsigned saddr = (unsigned)__cvta_generic_to_shared(smem_dst);
    asm volatile("cp.async.cg.shared.global [%0], [%1], 16;" :: "r"(saddr), "l"(gmem_src));
}
#define CP_COMMIT() asm volatile("cp.async.commit_group;")
#define CP_WAIT1()  asm volatile("cp.async.wait_group 1;")
#define GROUP_BAR(id) asm volatile("bar.sync %0, 128;" :: "r"(id) : "memory")

// =====================================================================
// Convert kernel: fp32 -> bf16x2-packed copies (one-time, elementwise).
// =====================================================================
#define CV0 (Bn * Dn / 2)
#define CV1 (CV0 + Hn * Dn / 2)
#define CV2 (CV1 + Dn * Hn / 2)
#define CV3 (CV2 + En * Wn * Rn * Dn / 2)
#define CV4 (CV3 + En * Wn * Hn * Rn / 2)
#define CV5 (CV4 + En * Wn * Rn * Hn / 2)
#define CV6 (CV5 + En * Wn * Dn * Rn / 2)

__global__ void __launch_bounds__(256)
convert_kernel(const float* __restrict__ z,  const float* __restrict__ w1,
               const float* __restrict__ w2, const float* __restrict__ a1,
               const float* __restrict__ b1, const float* __restrict__ a2,
               const float* __restrict__ b2) {
    for (int idx = blockIdx.x * 256 + threadIdx.x; idx < CV6; idx += gridDim.x * 256) {
        const float2* s; unsigned* d; int off;
        if      (idx < CV0) { s = (const float2*)z;  d = g_z_bf;  off = idx; }
        else if (idx < CV1) { s = (const float2*)w1; d = g_w1_bf; off = idx - CV0; }
        else if (idx < CV2) { s = (const float2*)w2; d = g_w2_bf; off = idx - CV1; }
        else if (idx < CV3) { s = (const float2*)a1; d = g_a1_bf; off = idx - CV2; }
        else if (idx < CV4) { s = (const float2*)b1; d = g_b1_bf; off = idx - CV3; }
        else if (idx < CV5) { s = (const float2*)a2; d = g_a2_bf; off = idx - CV4; }
        else                { s = (const float2*)b2; d = g_b2_bf; off = idx - CV5; }
        float2 v = s[off];
        d[off] = pack_bf16(v.x, v.y);
    }
}

// =====================================================================
// Side work A: logits/softmax/top-cand (fp32), one warp per token.
// =====================================================================
__device__ void logits_body(int b, int lane,
                            const float* __restrict__ z,
                            const float* __restrict__ proto,
                            const float* __restrict__ ebias,
                            const int* __restrict__ topk_p,
                            const int* __restrict__ ban_p,
                            const float* __restrict__ tau_p,
                            const float* __restrict__ eps_p,
                            float* __restrict__ d_out) {
    const float* zr = z + (size_t)b * Dn;

    float acc[En];
    #pragma unroll
    for (int e = 0; e < En; e++) acc[e] = 0.0f;
    for (int d = lane; d < Dn; d += 32) {
        float zv = zr[d];
        #pragma unroll
        for (int e = 0; e < En; e++) acc[e] += zv * proto[e * Dn + d];
    }
    #pragma unroll
    for (int e = 0; e < En; e++) acc[e] = warp_reduce(acc[e]);

    if (lane != 0) return;

    int k = *topk_p; if (k > En) k = En; if (k > MAXK) k = MAXK; if (k < 1) k = 1;
    int cand_k = 4 * k; if (cand_k < k) cand_k = k; if (cand_k > En) cand_k = En;
    int ban = *ban_p;
    float inv_tau = 1.0f / fmaxf(*tau_p, 1e-6f);
    float eps = *eps_p;

    float lg[En];
    float mx = -1e30f;
    #pragma unroll
    for (int e = 0; e < En; e++) {
        float v = acc[e] * inv_tau + ebias[e];
        if (e == ban) v = -1e9f;
        lg[e] = v;
        mx = fmaxf(mx, v);
    }
    float sum = 0.0f;
    #pragma unroll
    for (int e = 0; e < En; e++) { lg[e] = expf(lg[e] - mx); sum += lg[e]; }
    float inv = 1.0f / sum;

    Outs O = make_outs(d_out, k);
    float pr[En];
    #pragma unroll
    for (int e = 0; e < En; e++) {
        pr[e] = (1.0f - eps) * (lg[e] * inv) + eps / (float)En;
        O.probs[b * En + e] = pr[e];
        O.mask[b * En + e]  = 0.0f;
    }

    bool used[En];
    #pragma unroll
    for (int e = 0; e < En; e++) used[e] = false;
    unsigned long long pk = 0ull;
    for (int j = 0; j < cand_k; j++) {
        float bv = -1e30f; int bi = 0;
        for (int e = 0; e < En; e++)
            if (!used[e] && pr[e] > bv) { bv = pr[e]; bi = e; }
        used[bi] = true;
        g_cand_val[b * CANDMAX + j] = bv;
        pk |= ((unsigned long long)bi) << (4 * j);
    }
    g_pack[b] = pk;

    for (int s = 0; s < k; s++) {
        g_assigned_idx[b * MAXK + s] = -1;
        g_assigned_w[b * MAXK + s]   = 0.0f;
        O.aidx[b * k + s] = -1.0f;
        O.aw[b * k + s]   = 0.0f;
        O.ev_e[s * Bn + b] = -1.0f;
        O.ev_a[s * Bn + b] = -1.0f;
    }
}

// =====================================================================
// Side work B: batched greedy capacity router (single warp).
// =====================================================================
__device__ void route_body(int lane,
                           const int* __restrict__ topk_p,
                           const int* __restrict__ cap_p,
                           float* __restrict__ d_out) {
    int k = *topk_p; if (k > En) k = En; if (k > MAXK) k = MAXK; if (k < 1) k = 1;
    int cand_k = 4 * k; if (cand_k < k) cand_k = k; if (cand_k > En) cand_k = En;
    int cap_lim = *cap_p; if (cap_lim < 1) cap_lim = 1;

    Outs O = make_outs(d_out, k);

    int cap = 0;
    unsigned closed = 0;
    int hits = 0;

    int t0 = 0;
    while (t0 < Bn) {
        const int t = t0 + lane;
        const bool has = (t < Bn);
        unsigned long long pk = has ? g_pack[t] : 0ull;

        unsigned take = 0, slotcand = 0;
        int nslots = 0, myhits = 0;
        if (has) {
            for (int j = 0; j < cand_k; j++) {
                int e = (int)((pk >> (4 * j)) & 15ull);
                if (!((closed >> e) & 1u) && nslots < k) {
                    take |= (1u << e);
                    slotcand |= ((unsigned)j) << (4 * nslots);
                    if (j > 0) myhits++;
                    nslots++;
                }
            }
        }

        unsigned mybits = 0;
        #pragma unroll
        for (int e = 0; e < En; e++) {
            unsigned bb = __ballot_sync(0xffffffffu, (take >> e) & 1u);
            if (lane == e) mybits = bb;
        }
        int cnt = __popc(mybits);

        bool viol = (lane < En) && !((closed >> lane) & 1u) && (cap + cnt > cap_lim);
        unsigned vm = __ballot_sync(0xffffffffu, viol);
        int pstar = 32;
        if (vm) {
            int myp = 32;
            if (viol) {
                int rem = cap_lim - cap;
                unsigned m = mybits;
                for (int i = 0; i < rem; i++) m &= m - 1;
                myp = __ffs(m) - 1;
            }
            #pragma unroll
            for (int off = 16; off; off >>= 1) {
                int o = __shfl_xor_sync(0xffffffffu, myp, off);
                myp = min(myp, o);
            }
            pstar = myp;
        }

        unsigned commit_prefix = (pstar >= 32) ? 0xffffffffu : ((1u << pstar) - 1u);
        if (lane < En) cap += __popc(mybits & commit_prefix);

        if (has && lane < pstar) {
            for (int s = 0; s < nslots; s++) {
                int j = (int)((slotcand >> (4 * s)) & 15u);
                int e = (int)((pk >> (4 * j)) & 15ull);
                float v = g_cand_val[t * CANDMAX + j];
                g_assigned_idx[t * MAXK + s] = e;
                g_assigned_w[t * MAXK + s]   = v;
                O.aidx[t * k + s] = (float)e;
                O.aw[t * k + s]   = v;
                O.ev_e[s * Bn + t] = (float)e;
                O.mask[t * En + e] = 1.0f;
            }
            hits += myhits;
        }

        closed = __ballot_sync(0xffffffffu, (lane < En) && (cap >= cap_lim)) & 0xffffu;
        t0 += pstar;
    }

    #pragma unroll
    for (int off = 16; off; off >>= 1) hits += __shfl_xor_sync(0xffffffffu, hits, off);
    if (lane == 0) O.chr[0] = (float)hits / (float)(Bn * k);
}

// =====================================================================
// Fused BF16 GEMM (128x128x32, 3-stage cp.async, R14-exact mainloop).
// SIDE==1: logits side blocks (one token per warp, R14 mapping).
// SIDE==2: router side block at bx==NX (by==0, warp 0).
// =====================================================================
#define TBM 128
#define TBN 128
#define TBK 32
#define PITCH 20
#define STG ((TBM + TBN) * PITCH)
#define NSTAGE 3

template <int ACT, int SIDE, int NX>
__global__ void __launch_bounds__(256, 2)
gemm_fused_kernel(const unsigned short* __restrict__ Abf,
                  const unsigned short* __restrict__ Wbf,
                  const float* __restrict__ bias, float* __restrict__ C,
                  unsigned* __restrict__ Cbf,
                  int M, int N, int K,
                  const float* __restrict__ z, const float* __restrict__ proto,
                  const float* __restrict__ ebias,
                  const int* __restrict__ topk_p, const int* __restrict__ ban_p,
                  const float* __restrict__ tau_p, const float* __restrict__ eps_p,
                  const int* __restrict__ cap_p,
                  float* __restrict__ d_out) {
    const int bx = blockIdx.x;
    const int by = blockIdx.y;
    const int tid = threadIdx.x;
    const int warp = tid >> 5;
    const int lane = tid & 31;

    if (bx >= NX) {
        if (SIDE == 1) {
            int blk = (bx - NX) * gridDim.y + by;
            int b = blk * 8 + warp;
            if (b < Bn)
                logits_body(b, lane, z, proto, ebias, topk_p, ban_p, tau_p, eps_p, d_out);
        } else if (SIDE == 2) {
            if (by == 0 && warp == 0)
                route_body(lane, topk_p, cap_p, d_out);
        }
        return;
    }

    extern __shared__ unsigned smem_u[];

    const int g  = lane >> 2;
    const int tg = lane & 3;
    const int wq  = warp & 3;
    const int wn2 = warp >> 2;

    float acc[2][8][4];
    #pragma unroll
    for (int i = 0; i < 2; i++)
        #pragma unroll
        for (int j = 0; j < 8; j++)
            #pragma unroll
            for (int c = 0; c < 4; c++) acc[i][j][c] = 0.0f;

    auto issue = [&](int buf, int kt) {
        unsigned* base = smem_u + buf * STG;
        const int k0 = kt * TBK;
        #pragma unroll
        for (int i = 0; i < 4; i++) {
            int c = tid + i * 256;
            int row = c >> 2, ch = c & 3;
            const unsigned short* src;
            if (row < TBM) src = Abf + (size_t)(by * TBM + row) * K + k0 + ch * 8;
            else           src = Wbf + (size_t)(bx * TBN + row - TBM) * K + k0 + ch * 8;
            cp_async16(base + row * PITCH + ch * 4, (const void*)src);
        }
    };

    const int KIT = K / TBK;
    issue(0, 0); CP_COMMIT();
    if (1 < KIT) { issue(1, 1); } CP_COMMIT();

    int buf = 0;
    for (int kt = 0; kt < KIT; kt++) {
        CP_WAIT1();
        __syncthreads();
        if (kt + 2 < KIT) {
            int nb = buf + 2; if (nb >= NSTAGE) nb -= NSTAGE;
            issue(nb, kt + 2);
        }
        CP_COMMIT();

        const unsigned* AsC = smem_u + buf * STG;
        const unsigned* BsC = AsC + TBM * PITCH;

        #pragma unroll
        for (int kk = 0; kk < 2; kk++) {
            unsigned afr[2][4];
            #pragma unroll
            for (int mi = 0; mi < 2; mi++) {
                int row = wq * 32 + mi * 16 + g;
                afr[mi][0] = AsC[row * PITCH + kk * 8 + tg];
                afr[mi][1] = AsC[(row + 8) * PITCH + kk * 8 + tg];
                afr[mi][2] = AsC[row * PITCH + kk * 8 + tg + 4];
                afr[mi][3] = AsC[(row + 8) * PITCH + kk * 8 + tg + 4];
            }
            unsigned bfr[8][2];
            #pragma unroll
            for (int ni = 0; ni < 8; ni++) {
                int col = wn2 * 64 + ni * 8 + g;
                bfr[ni][0] = BsC[col * PITCH + kk * 8 + tg];
                bfr[ni][1] = BsC[col * PITCH + kk * 8 + tg + 4];
            }
            #pragma unroll
            for (int mi = 0; mi < 2; mi++)
                #pragma unroll
                for (int ni = 0; ni < 8; ni++)
                    mma_bf16(acc[mi][ni], afr[mi], bfr[ni]);
        }
        buf++; if (buf >= NSTAGE) buf = 0;
    }

    #pragma unroll
    for (int mi = 0; mi < 2; mi++) {
        int row0 = by * TBM + wq * 32 + mi * 16 + g;
        #pragma unroll
        for (int ni = 0; ni < 8; ni++) {
            int col = bx * TBN + wn2 * 64 + ni * 8 + 2 * tg;
            float b0 = bias[col], b1 = bias[col + 1];
            float v0 = acc[mi][ni][0] + b0;
            float v1 = acc[mi][ni][1] + b1;
            float v2 = acc[mi][ni][2] + b0;
            float v3 = acc[mi][ni][3] + b1;
            if (ACT) { v0 = silu_f(v0); v1 = silu_f(v1); v2 = silu_f(v2); v3 = silu_f(v3); }
            *(float2*)(&C[(size_t)row0 * N + col])       = make_float2(v0, v1);
            *(float2*)(&C[(size_t)(row0 + 8) * N + col]) = make_float2(v2, v3);
            if (ACT) {
                Cbf[((size_t)row0 * N + col) >> 1]       = pack_bf16(v0, v1);
                Cbf[((size_t)(row0 + 8) * N + col) >> 1] = pack_bf16(v2, v3);
            }
        }
    }
}

// =====================================================================
// Adapter kernel (R13/14 structure; phase 6 + final combine vectorized:
// each thread owns 4 consecutive d's -> LDG.128/STG.128 for opre/out).
// Per-element arithmetic identical -> bit-identical results.
// =====================================================================
__global__ void __launch_bounds__(256)
adapter_kernel(const float* __restrict__ z,
               const float* __restrict__ ak,
               const unsigned* __restrict__ a1b, const unsigned* __restrict__ b1b,
               const unsigned* __restrict__ a2b, const unsigned* __restrict__ b2b,
               const int* __restrict__ topk_p,
               float* __restrict__ d_out) {
    __shared__ float s_z[Dn];
    __shared__ float s_hp[Hn];
    __shared__ float s_t1[2][Rn];
    __shared__ float s_t2p[2][4][Rn];
    __shared__ float s_sc[2][Wn];
    __shared__ int   s_base[2];
    __shared__ float s_wgt[2];
    __shared__ int   s_valid[2];

    const int b = blockIdx.x;
    const int tid = threadIdx.x;
    const int lane = tid & 31;
    const int warp = tid >> 5;
    const int group = warp >> 2;
    const int wig = warp & 3;
    const int gt = tid & 127;
    const int gbar = 1 + group;

    int k = *topk_p; if (k > En) k = En; if (k > MAXK) k = MAXK; if (k < 1) k = 1;
    Outs O = make_outs(d_out, k);

    for (int i = tid; i < Dn / 4; i += 256)
        ((float4*)s_z)[i] = ((const float4*)(z + (size_t)b * Dn))[i];
    for (int i = tid; i < Hn / 4; i += 256)
        ((float4*)s_hp)[i] = ((const float4*)(g_hpre + (size_t)b * Hn))[i];

    // thread owns d = 4*tid .. 4*tid+3
    float4 opre4 = ((const float4*)(g_outpre + (size_t)b * Dn))[tid];
    float4 accd4 = make_float4(0.f, 0.f, 0.f, 0.f);
    __syncthreads();

    for (int s0 = 0; s0 < k; s0 += 2) {
        const int sA = s0 + group;
        const bool act = (sA < k);
        int e = -1;
        float wgt = 0.0f;
        if (act) {
            e   = g_assigned_idx[b * MAXK + sA];
            wgt = g_assigned_w[b * MAXK + sA];
        }
        const bool valid = act && (e >= 0);

        // phase 1: adapter-key dots (fp32, float4)
        if (valid) {
            const float4* akr = (const float4*)(ak + (size_t)(e * Wn + wig) * Dn);
            float p = 0.0f;
            #pragma unroll
            for (int i = 0; i < Dn / 128; i++) {
                int idx = lane + i * 32;
                float4 a = akr[idx];
                float4 zz = ((const float4*)s_z)[idx];
                p += a.x * zz.x + a.y * zz.y + a.z * zz.z + a.w * zz.w;
            }
            p = warp_reduce(p);
            if (lane == 0) s_sc[group][wig] = p;
        }
        GROUP_BAR(gbar);

        // phase 2: argmax + publish
        if (gt == 0) {
            if (valid) {
                float bv = s_sc[group][0]; int bi = 0;
                #pragma unroll
                for (int w2 = 1; w2 < Wn; w2++)
                    if (s_sc[group][w2] > bv) { bv = s_sc[group][w2]; bi = w2; }
                s_base[group] = e * Wn + bi;
                s_wgt[group] = wgt;
                s_valid[group] = 1;
                O.ev_a[sA * Bn + b] = (float)bi;
            } else {
                s_valid[group] = 0;
            }
        }
        GROUP_BAR(gbar);

        const int base = s_base[group];

        // phase 3: t1[r] = z . A1[base, r, :]  (bf16 weights, warp = 2 r's)
        if (valid) {
            const uint2* A1r0 = (const uint2*)a1b + ((size_t)base * Rn + 2 * wig) * (Dn / 4);
            const uint2* A1r1 = A1r0 + (Dn / 4);
            float q0 = 0.0f, q1 = 0.0f;
            #pragma unroll
            for (int i = 0; i < Dn / 128; i++) {
                int idx = lane + i * 32;
                float4 zz = ((const float4*)s_z)[idx];
                uint2 u0 = A1r0[idx], u1 = A1r1[idx];
                q0 += zz.x * bf_lo(u0.x) + zz.y * bf_hi(u0.x)
                    + zz.z * bf_lo(u0.y) + zz.w * bf_hi(u0.y);
                q1 += zz.x * bf_lo(u1.x) + zz.y * bf_hi(u1.x)
                    + zz.z * bf_lo(u1.y) + zz.w * bf_hi(u1.y);
            }
            q0 = warp_reduce(q0);
            q1 = warp_reduce(q1);
            if (lane == 0) { s_t1[group][2 * wig] = q0; s_t1[group][2 * wig + 1] = q1; }
        }
        GROUP_BAR(gbar);

        // phase 4' (merged): warp owns h pairs [wig*256, wig*256+256).
        if (valid) {
            float t1r[Rn];
            #pragma unroll
            for (int r = 0; r < Rn; r++) t1r[r] = s_t1[group][r];
            float t2p[Rn];
            #pragma unroll
            for (int r = 0; r < Rn; r++) t2p[r] = 0.0f;
            const uint4* B1 = (const uint4*)b1b + (size_t)base * Hn;
            const unsigned* A2 = a2b + (size_t)base * Rn * (Hn / 2);
            #pragma unroll
            for (int i = 0; i < 8; i++) {
                int hp = wig * 256 + lane + i * 32;
                float2 h2 = *(const float2*)&s_hp[2 * hp];
                uint4 q0 = B1[2 * hp];
                uint4 q1 = B1[2 * hp + 1];
                float d10 = t1r[0] * bf_lo(q0.x) + t1r[1] * bf_hi(q0.x)
                          + t1r[2] * bf_lo(q0.y) + t1r[3] * bf_hi(q0.y)
                          + t1r[4] * bf_lo(q0.z) + t1r[5] * bf_hi(q0.z)
                          + t1r[6] * bf_lo(q0.w) + t1r[7] * bf_hi(q0.w);
                float d11 = t1r[0] * bf_lo(q1.x) + t1r[1] * bf_hi(q1.x)
                          + t1r[2] * bf_lo(q1.y) + t1r[3] * bf_hi(q1.y)
                          + t1r[4] * bf_lo(q1.z) + t1r[5] * bf_hi(q1.z)
                          + t1r[6] * bf_lo(q1.w) + t1r[7] * bf_hi(q1.w);
                float hv0 = silu_f(h2.x + d10 * SCALE_C);
                float hv1 = silu_f(h2.y + d11 * SCALE_C);
                #pragma unroll
                for (int r = 0; r < Rn; r++) {
                    unsigned u = A2[r * (Hn / 2) + hp];
                    t2p[r] += hv0 * bf_lo(u) + hv1 * bf_hi(u);
                }
            }
            #pragma unroll
            for (int r = 0; r < Rn; r++) t2p[r] = warp_reduce(t2p[r]);
            if (lane < Rn) s_t2p[group][wig][lane] = t2p[lane];
        }
        __syncthreads();

        // phase 6: accumulate both groups (thread owns 4 consecutive d's)
        #pragma unroll
        for (int gg = 0; gg < 2; gg++) {
            if (s_valid[gg]) {
                const int bs = s_base[gg];
                const float wg = s_wgt[gg];
                float t2r[Rn];
                #pragma unroll
                for (int r = 0; r < Rn; r++)
                    t2r[r] = s_t2p[gg][0][r] + s_t2p[gg][1][r]
                           + s_t2p[gg][2][r] + s_t2p[gg][3][r];
                const uint4* B2q = (const uint4*)b2b + (size_t)bs * Dn;
                float dv[4];
                #pragma unroll
                for (int j = 0; j < 4; j++) {
                    uint4 q = B2q[4 * tid + j];
                    dv[j] = t2r[0] * bf_lo(q.x) + t2r[1] * bf_hi(q.x)
                          + t2r[2] * bf_lo(q.y) + t2r[3] * bf_hi(q.y)
                          + t2r[4] * bf_lo(q.z) + t2r[5] * bf_hi(q.z)
                          + t2r[6] * bf_lo(q.w) + t2r[7] * bf_hi(q.w);
                }
                accd4.x += wg * (opre4.x + dv[0] * SCALE_C);
                accd4.y += wg * (opre4.y + dv[1] * SCALE_C);
                accd4.z += wg * (opre4.z + dv[2] * SCALE_C);
                accd4.w += wg * (opre4.w + dv[3] * SCALE_C);
            }
        }
        __syncthreads();
    }

    float4 zz = ((const float4*)s_z)[tid];
    float4 outv;
    outv.x = zz.x + accd4.x;
    outv.y = zz.y + accd4.y;
    outv.z = zz.z + accd4.z;
    outv.w = zz.w + accd4.w;
    ((float4*)(O.z + (size_t)b * Dn))[tid] = outv;
}

// =====================================================================
// launch  (exact R14 structure = best measured config)
// =====================================================================
extern "C" void kernel_launch(void* const* d_in, const int* in_sizes, int n_in,
                              void* d_out, int out_size) {
    const float* z     = (const float*)d_in[0];
    const int*   topk  = (const int*)  d_in[1];
    const int*   cap   = (const int*)  d_in[2];
    const int*   ban   = (const int*)  d_in[3];
    const float* tau   = (const float*)d_in[4];
    const float* eps   = (const float*)d_in[5];
    const float* fc1w  = (const float*)d_in[6];
    const float* fc1b  = (const float*)d_in[7];
    const float* fc2w  = (const float*)d_in[8];
    const float* fc2b  = (const float*)d_in[9];
    const float* proto = (const float*)d_in[10];
    const float* ak    = (const float*)d_in[11];
    const float* ebias = (const float*)d_in[12];
    const float* a1    = (const float*)d_in[13];
    const float* b1    = (const float*)d_in[14];
    const float* a2    = (const float*)d_in[15];
    const float* b2    = (const float*)d_in[16];
    float* out = (float*)d_out;

    float *hpre_ptr, *outpre_ptr;
    unsigned *zb, *w1b, *w2b, *hpb, *a1b, *b1b, *a2b, *b2b;
    cudaGetSymbolAddress((void**)&hpre_ptr, g_hpre);
    cudaGetSymbolAddress((void**)&outpre_ptr, g_outpre);
    cudaGetSymbolAddress((void**)&zb,  g_z_bf);
    cudaGetSymbolAddress((void**)&w1b, g_w1_bf);
    cudaGetSymbolAddress((void**)&w2b, g_w2_bf);
    cudaGetSymbolAddress((void**)&hpb, g_hpre_bf);
    cudaGetSymbolAddress((void**)&a1b, g_a1_bf);
    cudaGetSymbolAddress((void**)&b1b, g_b1_bf);
    cudaGetSymbolAddress((void**)&a2b, g_a2_bf);
    cudaGetSymbolAddress((void**)&b2b, g_b2_bf);

    const int gemm_smem = NSTAGE * STG * sizeof(unsigned);  // 61440
    cudaFuncSetAttribute((const void*)gemm_fused_kernel<1, 1, 16>,
                         cudaFuncAttributeMaxDynamicSharedMemorySize, gemm_smem);
    cudaFuncSetAttribute((const void*)gemm_fused_kernel<0, 2, 8>,
                         cudaFuncAttributeMaxDynamicSharedMemorySize, gemm_smem);

    // 0) one-time fp32 -> bf16 conversion
    convert_kernel<<<2048, 256>>>(z, fc1w, fc2w, a1, b1, a2, b2);

    // 1) h_pre = silu(z @ fc1_w^T + fc1_b) (+ bf16 copy) + logits side work
    //    grid: 16 gemm n-cols (2048/128) x 16 m-rows + 16 logits cols (R14)
    gemm_fused_kernel<1, 1, 16><<<dim3(32, 16), 256, gemm_smem>>>(
        (const unsigned short*)zb, (const unsigned short*)w1b, fc1b,
        hpre_ptr, hpb, Bn, Hn, Dn,
        z, proto, ebias, topk, ban, tau, eps, cap, out);

    // 2) out_pre = h_pre @ fc2_w^T + fc2_b + router side block
    gemm_fused_kernel<0, 2, 8><<<dim3(9, 16), 256, gemm_smem>>>(
        (const unsigned short*)hpb, (const unsigned short*)w2b, fc2b,
        outpre_ptr, nullptr, Bn, Dn, Hn,
        z, proto, ebias, topk, ban, tau, eps, cap, out);

    // 3) adapter select + LoRA deltas + final combine
    adapter_kernel<<<Bn, 256>>>(z, ak, a1b, b1b, a2b, b2b, topk, out);
}